// round 1
// baseline (speedup 1.0000x reference)
#include <cuda_runtime.h>
#include <cuda_bf16.h>

// out[b,r] = sum_d [ -0.5*((x-mu)/sig)^2 - log(sig) - LOG_SQRT_2PI ] + prior[r]*2D
// Factorized as GEMM: out[b,r] = sum_k Xa[b,k]*G[k,r] + C[r]
//   Xa[b,k] = x[b,k]           (k < 512)   x = concat(sbjs, objs)
//           = x[b,k-512]^2     (k >= 512)
//   G[k,r]  = mu[r,k]/sig^2    (k < 512)
//           = -0.5/sig^2       (k >= 512)
//   C[r]    = sum_d(-0.5*mu^2/sig^2 - log sig) - 512*LOG_SQRT_2PI + 512*prior[r]

#define BATCH   4096
#define EMB     256
#define TWO_D   512
#define NREL    128
#define KDIM    1024

#define BM 32
#define BN 128
#define BK 32
#define NTHREADS 256

__device__ float g_G[KDIM * NREL];   // [k][r], row-major, 512 KB
__device__ float g_C[NREL];

// ---------------------------------------------------------------------------
// Precompute G and C. One block per relation r; coalesced reads of mu/sigma.
// ---------------------------------------------------------------------------
__global__ void __launch_bounds__(256) nb_precompute(
    const float* __restrict__ mus,
    const float* __restrict__ sigmas,
    const float* __restrict__ priors)
{
    const int r = blockIdx.x;      // 0..127
    const int t = threadIdx.x;     // 0..255
    __shared__ float red[256];

    float csum = 0.0f;
    #pragma unroll
    for (int d = t; d < TWO_D; d += 256) {
        float mu = mus[r * TWO_D + d];
        float s  = sigmas[r * TWO_D + d];
        float inv = 1.0f / (s * s);
        g_G[d * NREL + r]            = mu * inv;      // linear coeff
        g_G[(TWO_D + d) * NREL + r]  = -0.5f * inv;   // quadratic coeff
        csum += -0.5f * mu * mu * inv - logf(s);
    }
    red[t] = csum;
    __syncthreads();
    #pragma unroll
    for (int s2 = 128; s2 > 0; s2 >>= 1) {
        if (t < s2) red[t] += red[t + s2];
        __syncthreads();
    }
    if (t == 0) {
        g_C[r] = red[0] - (float)TWO_D * 0.9189385332046727f
                        + priors[r] * (float)TWO_D;
    }
}

// ---------------------------------------------------------------------------
// Main GEMM. grid = 128 blocks (one BM=32 stripe each, full N=128).
// f32x2 packed FMA over the N dimension (2 outputs per fma.rn.f32x2).
// ---------------------------------------------------------------------------
__device__ __forceinline__ void fma2(unsigned long long& acc,
                                     unsigned long long a,
                                     unsigned long long b)
{
    asm("fma.rn.f32x2 %0, %1, %2, %0;" : "+l"(acc) : "l"(a), "l"(b));
}

__device__ __forceinline__ float2 unpack2(unsigned long long v)
{
    float2 f;
    asm("mov.b64 {%0, %1}, %2;" : "=f"(f.x), "=f"(f.y) : "l"(v));
    return f;
}

__global__ void __launch_bounds__(NTHREADS) nb_gemm(
    const float* __restrict__ sbjs,
    const float* __restrict__ objs,
    float* __restrict__ out)
{
    __shared__ float Xs[BK][BM + 2];   // transposed X tile, pad->34 (8B-aligned rows)
    __shared__ float Gs[BK][BN];       // G tile (contiguous copy of g_G rows)
    __shared__ float Cs[BN];

    const int tid = threadIdx.x;
    const int b0  = blockIdx.x * BM;
    const int tx  = tid & 15;          // 0..15 -> N groups
    const int ty  = tid >> 4;          // 0..15 -> M pairs

    if (tid < NREL) Cs[tid] = g_C[tid];

    // per-thread microtile: 2 M-rows x 8 N-cols, packed as 2x4 f32x2 accumulators
    unsigned long long acc[2][4];
    #pragma unroll
    for (int i = 0; i < 2; i++)
        #pragma unroll
        for (int j = 0; j < 4; j++) acc[i][j] = 0ull;

    // ---- prefetch registers for the software pipeline ----
    float4 xPre;
    float4 gPre[4];
    int xRow = tid >> 3;       // 0..31
    int xC4  = tid & 7;        // 0..7  (float4 column within the BK=32 slab)

    auto load_tile = [&](int k0, float4& xp, float4* gp) {
        // X slab: rows b0..b0+31, k-cols k0..k0+31, from sbjs/objs (+square)
        int region = k0 >> 8;                              // 0..3
        const float4* src = (const float4*)((region & 1) ? objs : sbjs);
        int colBase4 = (k0 & 255) >> 2;                    // float4 offset in region
        float4 v = src[(b0 + xRow) * (EMB / 4) + colBase4 + xC4];
        if (k0 >= TWO_D) { v.x *= v.x; v.y *= v.y; v.z *= v.z; v.w *= v.w; }
        xp = v;
        // G slab: contiguous 32x128 floats = 1024 float4
        const float4* Gsrc = (const float4*)(g_G + k0 * NREL);
        #pragma unroll
        for (int i = 0; i < 4; i++) gp[i] = Gsrc[tid + 256 * i];
    };

    load_tile(0, xPre, gPre);

    for (int t = 0; t < KDIM / BK; t++) {
        // store prefetched tile to smem
        {
            int kl = xC4 * 4;
            Xs[kl + 0][xRow] = xPre.x;
            Xs[kl + 1][xRow] = xPre.y;
            Xs[kl + 2][xRow] = xPre.z;
            Xs[kl + 3][xRow] = xPre.w;
            float4* Gdst = (float4*)Gs;
            #pragma unroll
            for (int i = 0; i < 4; i++) Gdst[tid + 256 * i] = gPre[i];
        }
        __syncthreads();

        if (t + 1 < KDIM / BK) load_tile((t + 1) * BK, xPre, gPre);

        #pragma unroll
        for (int kk = 0; kk < BK; kk++) {
            // 8 G values as 4 packed f32x2 (conflict-free: 16 lanes x 16B contiguous)
            ulonglong2 gA = *(const ulonglong2*)&Gs[kk][tx * 4];
            ulonglong2 gB = *(const ulonglong2*)&Gs[kk][64 + tx * 4];
            #pragma unroll
            for (int i = 0; i < 2; i++) {
                float xv = Xs[kk][ty * 2 + i];
                unsigned long long x2;
                asm("mov.b64 %0, {%1, %1};" : "=l"(x2) : "f"(xv));
                fma2(acc[i][0], x2, gA.x);
                fma2(acc[i][1], x2, gA.y);
                fma2(acc[i][2], x2, gB.x);
                fma2(acc[i][3], x2, gB.y);
            }
        }
        __syncthreads();
    }

    // ---- epilogue: add C[r], store ----
    #pragma unroll
    for (int i = 0; i < 2; i++) {
        int row = b0 + ty * 2 + i;
        float2 a0 = unpack2(acc[i][0]);
        float2 a1 = unpack2(acc[i][1]);
        float2 b0v = unpack2(acc[i][2]);
        float2 b1v = unpack2(acc[i][3]);
        float4 o;
        int c = tx * 4;
        o.x = a0.x + Cs[c + 0];
        o.y = a0.y + Cs[c + 1];
        o.z = a1.x + Cs[c + 2];
        o.w = a1.y + Cs[c + 3];
        *(float4*)&out[row * NREL + c] = o;
        c = 64 + tx * 4;
        o.x = b0v.x + Cs[c + 0];
        o.y = b0v.y + Cs[c + 1];
        o.z = b1v.x + Cs[c + 2];
        o.w = b1v.y + Cs[c + 3];
        *(float4*)&out[row * NREL + c] = o;
    }
}

extern "C" void kernel_launch(void* const* d_in, const int* in_sizes, int n_in,
                              void* d_out, int out_size)
{
    const float* sbjs   = (const float*)d_in[0];
    const float* objs   = (const float*)d_in[1];
    const float* mus    = (const float*)d_in[2];
    const float* sigmas = (const float*)d_in[3];
    const float* priors = (const float*)d_in[4];
    float* out = (float*)d_out;

    nb_precompute<<<NREL, 256>>>(mus, sigmas, priors);
    nb_gemm<<<BATCH / BM, NTHREADS>>>(sbjs, objs, out);
}

// round 3
// speedup vs baseline: 2.2737x; 2.2737x over previous
#include <cuda_runtime.h>
#include <cuda_bf16.h>
#include <cstdint>

// out[b,r] = sum_k Xa[b,k]*G[k,r] + C[r]
//   Xa[b,k] = x[b,k] (k<512), x[b,k-512]^2 (k>=512), x = concat(sbjs, objs)
//   G[k,r]  = mu[r,k]/sig^2 (k<512), -0.5/sig^2 (k>=512)
//   C[r]    = sum_d(-0.5*mu^2/sig^2 - log sig) - 512*LOG_SQRT_2PI + 512*prior[r]
// GEMM via mma.sync m16n8k16 bf16 (sm_80+ PTX -> HMMA on sm_103; tcgen05 is
// not accepted by this harness's ptxas target). A split hi/lo bf16 for fp32-
// level accuracy; fp32 register accumulators.

#define BATCH 4096
#define EMB   256
#define TWO_D 512
#define NREL  128
#define KDIM  1024

#define ROWB   144              // smem row pitch bytes (64 data halves + 8 pad)
#define A_TILE (32 * ROWB)      // 4608 B  (one 32x64 bf16 tile)
#define B_TILE (64 * ROWB)      // 9216 B  (one 64x64 bf16 tile)

__device__ __nv_bfloat16 g_B[NREL * KDIM];   // [r][k] bf16, 256 KB (L2-resident)
__device__ float g_C[NREL];

__device__ __forceinline__ uint32_t smem_u32(const void* p) {
    uint32_t a;
    asm("{ .reg .u64 t; cvta.to.shared.u64 t, %1; cvt.u32.u64 %0, t; }"
        : "=r"(a) : "l"(p));
    return a;
}

#define LDSM4(r, addr) \
    asm volatile("ldmatrix.sync.aligned.m8n8.x4.shared.b16 {%0,%1,%2,%3}, [%4];" \
        : "=r"((r)[0]), "=r"((r)[1]), "=r"((r)[2]), "=r"((r)[3]) : "r"(addr))

__device__ __forceinline__ void mma16816(float* c, const uint32_t* a,
                                         uint32_t b0, uint32_t b1) {
    asm("mma.sync.aligned.m16n8k16.row.col.f32.bf16.bf16.f32 "
        "{%0,%1,%2,%3}, {%4,%5,%6,%7}, {%8,%9}, {%0,%1,%2,%3};"
        : "+f"(c[0]), "+f"(c[1]), "+f"(c[2]), "+f"(c[3])
        : "r"(a[0]), "r"(a[1]), "r"(a[2]), "r"(a[3]), "r"(b0), "r"(b1));
}

#define CP_ASYNC16(dst, src) \
    asm volatile("cp.async.cg.shared.global [%0], [%1], 16;" \
        :: "r"(dst), "l"(src) : "memory")
#define CP_COMMIT() asm volatile("cp.async.commit_group;" ::: "memory")
#define CP_WAIT0()  asm volatile("cp.async.wait_group 0;" ::: "memory")

// ---------------------------------------------------------------------------
__global__ void __launch_bounds__(256) nb_precompute(
    const float* __restrict__ mus,
    const float* __restrict__ sigmas,
    const float* __restrict__ priors)
{
    const int r = blockIdx.x;
    const int t = threadIdx.x;
    __shared__ float red[256];

    float csum = 0.0f;
    #pragma unroll
    for (int d = t; d < TWO_D; d += 256) {
        float mu = mus[r * TWO_D + d];
        float s  = sigmas[r * TWO_D + d];
        float inv = 1.0f / (s * s);
        g_B[r * KDIM + d]         = __float2bfloat16_rn(mu * inv);
        g_B[r * KDIM + TWO_D + d] = __float2bfloat16_rn(-0.5f * inv);
        csum += -0.5f * mu * mu * inv - logf(s);
    }
    red[t] = csum;
    __syncthreads();
    #pragma unroll
    for (int s2 = 128; s2 > 0; s2 >>= 1) {
        if (t < s2) red[t] += red[t + s2];
        __syncthreads();
    }
    if (t == 0) {
        g_C[r] = red[0] - (float)TWO_D * 0.9189385332046727f
                        + priors[r] * (float)TWO_D;
    }
}

// ---------------------------------------------------------------------------
// 256 CTAs = 128 M-tiles (BM=32) x 2 N-tiles (BN=64). 128 threads = 4 warps,
// warp tile 16x32 (2x2 warp grid). K processed in 16 chunks of 64 bf16 cols;
// each chunk contributes A_hi and A_lo MMAs against the same B tile.
// ---------------------------------------------------------------------------
__global__ void __launch_bounds__(128) nb_mma(
    const float* __restrict__ sbjs,
    const float* __restrict__ objs,
    float* __restrict__ out)
{
    __shared__ __align__(16) char smA[2 * 2 * A_TILE];  // [stage][hi/lo]
    __shared__ __align__(16) char smB[2 * B_TILE];      // [stage]

    const int tid  = threadIdx.x;
    const int lane = tid & 31;
    const int wid  = tid >> 5;
    const int wm   = wid & 1;          // 0/1 -> m offset 0/16
    const int wn   = wid >> 1;         // 0/1 -> n offset 0/32
    const int mt   = blockIdx.x >> 1;
    const int nt   = blockIdx.x & 1;
    const int b0   = mt * 32;
    const int n0   = nt * 64;

    const uint32_t sA = smem_u32(smA);
    const uint32_t sB = smem_u32(smB);

    float acc[4][4];
    #pragma unroll
    for (int f = 0; f < 4; f++)
        #pragma unroll
        for (int i = 0; i < 4; i++) acc[f][i] = 0.0f;

    // load-index helpers
    const int xrow  = tid >> 2;        // 0..31
    const int xc    = tid & 3;         // 0..3
    const int brow  = tid >> 1;        // 0..63
    const int bseg0 = (tid & 1) * 4;   // 0/4

    float4 xv[4];

    auto ldgX = [&](int c) {
        const float4* src = (const float4*)(((c >> 2) & 1) ? objs : sbjs);
        const float4* p = src + (size_t)(b0 + xrow) * (EMB / 4)
                              + (c & 3) * 16 + xc;
        #pragma unroll
        for (int j = 0; j < 4; j++) xv[j] = p[4 * j];
    };
    auto cpB = [&](int c, int stage) {
        const __nv_bfloat16* gp = g_B + (size_t)(n0 + brow) * KDIM
                                      + c * 64 + bseg0 * 8;
        uint32_t dst = sB + stage * B_TILE + brow * ROWB + bseg0 * 16;
        #pragma unroll
        for (int j = 0; j < 4; j++)
            CP_ASYNC16(dst + j * 16, gp + j * 8);
        CP_COMMIT();
    };

    ldgX(0);
    cpB(0, 0);

    // ldmatrix lane addresses (stage 0 base; add stage offsets per iter)
    const uint32_t aBase = sA + (wm * 16 + (lane & 15)) * ROWB
                              + (lane >> 4) * 16;
    const uint32_t bBase = sB + (wn * 32 + (lane & 7) + ((lane >> 4) << 3)) * ROWB
                              + ((lane >> 3) & 1) * 16;

    for (int c = 0; c < 16; c++) {
        const int stage = c & 1;
        const uint32_t sAst = sA + stage * (2 * A_TILE);
        const bool sq = (c >= 8);

        // convert + STS of X chunk c
        #pragma unroll
        for (int j = 0; j < 4; j++) {
            float4 v = xv[j];
            if (sq) { v.x *= v.x; v.y *= v.y; v.z *= v.z; v.w *= v.w; }
            __nv_bfloat16 h0 = __float2bfloat16_rn(v.x);
            __nv_bfloat16 h1 = __float2bfloat16_rn(v.y);
            __nv_bfloat16 h2 = __float2bfloat16_rn(v.z);
            __nv_bfloat16 h3 = __float2bfloat16_rn(v.w);
            __nv_bfloat16 l0 = __float2bfloat16_rn(v.x - __bfloat162float(h0));
            __nv_bfloat16 l1 = __float2bfloat16_rn(v.y - __bfloat162float(h1));
            __nv_bfloat16 l2 = __float2bfloat16_rn(v.z - __bfloat162float(h2));
            __nv_bfloat16 l3 = __float2bfloat16_rn(v.w - __bfloat162float(h3));
            uint2 hi, lo;
            hi.x = (uint32_t)__bfloat16_as_ushort(h0)
                 | ((uint32_t)__bfloat16_as_ushort(h1) << 16);
            hi.y = (uint32_t)__bfloat16_as_ushort(h2)
                 | ((uint32_t)__bfloat16_as_ushort(h3) << 16);
            lo.x = (uint32_t)__bfloat16_as_ushort(l0)
                 | ((uint32_t)__bfloat16_as_ushort(l1) << 16);
            lo.y = (uint32_t)__bfloat16_as_ushort(l2)
                 | ((uint32_t)__bfloat16_as_ushort(l3) << 16);
            int off = xrow * ROWB + (xc + 4 * j) * 8;
            *(uint2*)(smA + stage * (2 * A_TILE) + off)          = hi;
            *(uint2*)(smA + stage * (2 * A_TILE) + A_TILE + off) = lo;
        }

        CP_WAIT0();              // B chunk c arrived
        __syncthreads();

        if (c < 15) {            // prefetch next chunk while MMAs run
            ldgX(c + 1);
            cpB(c + 1, stage ^ 1);
        }

        const uint32_t aH = aBase + stage * (2 * A_TILE);
        const uint32_t aL = aH + A_TILE;
        const uint32_t bA = bBase + stage * B_TILE;

        #pragma unroll
        for (int kk = 0; kk < 4; kk++) {
            uint32_t ah[4], al[4], br0[4], br1[4];
            LDSM4(ah, aH + kk * 32);
            LDSM4(al, aL + kk * 32);
            LDSM4(br0, bA + kk * 32);                 // n +0..15
            LDSM4(br1, bA + 16 * ROWB + kk * 32);     // n +16..31
            mma16816(acc[0], ah, br0[0], br0[1]);
            mma16816(acc[1], ah, br0[2], br0[3]);
            mma16816(acc[2], ah, br1[0], br1[1]);
            mma16816(acc[3], ah, br1[2], br1[3]);
            mma16816(acc[0], al, br0[0], br0[1]);
            mma16816(acc[1], al, br0[2], br0[3]);
            mma16816(acc[2], al, br1[0], br1[1]);
            mma16816(acc[3], al, br1[2], br1[3]);
        }
    }

    // ---- epilogue: add C[r], store fp32 ----
    const int r0 = b0 + wm * 16 + (lane >> 2);
    #pragma unroll
    for (int f = 0; f < 4; f++) {
        int col = n0 + wn * 32 + f * 8 + (lane & 3) * 2;
        float ca = g_C[col];
        float cb = g_C[col + 1];
        float2 v0 = make_float2(acc[f][0] + ca, acc[f][1] + cb);
        float2 v1 = make_float2(acc[f][2] + ca, acc[f][3] + cb);
        *(float2*)&out[(size_t)r0 * NREL + col]       = v0;
        *(float2*)&out[(size_t)(r0 + 8) * NREL + col] = v1;
    }
}

extern "C" void kernel_launch(void* const* d_in, const int* in_sizes, int n_in,
                              void* d_out, int out_size)
{
    const float* sbjs   = (const float*)d_in[0];
    const float* objs   = (const float*)d_in[1];
    const float* mus    = (const float*)d_in[2];
    const float* sigmas = (const float*)d_in[3];
    const float* priors = (const float*)d_in[4];
    float* out = (float*)d_out;

    nb_precompute<<<NREL, 256>>>(mus, sigmas, priors);
    nb_mma<<<(BATCH / 32) * (NREL / 64), 128>>>(sbjs, objs, out);
}

// round 4
// speedup vs baseline: 2.4796x; 1.0906x over previous
#include <cuda_runtime.h>
#include <cuda_bf16.h>
#include <cstdint>

// out[b,r] = sum_k Xa[b,k]*G[k,r] + C[r]
//   Xa[b,k] = x[b,k] (k<512), x[b,k-512]^2 (k>=512), x = concat(sbjs, objs)
//   G[k,r]  = mu[r,k]/sig^2 (k<512), -0.5/sig^2 (k>=512)
//   C[r]    = sum_d(-0.5*mu^2/sig^2 - log sig) - 512*LOG_SQRT_2PI + 512*prior[r]
// mma.sync m16n8k16 bf16, A split hi/lo for fp32-level accuracy.
// K-split x4 across CTAs (grid 1024) for occupancy; fp32 partials in device
// scratch; tiny reduce kernel sums partials + C.

#define BATCH 4096
#define EMB   256
#define TWO_D 512
#define NREL  128
#define KDIM  1024
#define KSPLIT 4

#define ROWB   144              // smem row pitch bytes (64 data halves + 8 pad)
#define A_TILE (32 * ROWB)      // 4608 B
#define B_TILE (64 * ROWB)      // 9216 B

__device__ __nv_bfloat16 g_B[NREL * KDIM];            // 256 KB (L2-resident)
__device__ float g_C[NREL];
__device__ float g_partial[KSPLIT * BATCH * NREL];    // 8 MB scratch

__device__ __forceinline__ uint32_t smem_u32(const void* p) {
    uint32_t a;
    asm("{ .reg .u64 t; cvta.to.shared.u64 t, %1; cvt.u32.u64 %0, t; }"
        : "=r"(a) : "l"(p));
    return a;
}

#define LDSM4(r, addr) \
    asm volatile("ldmatrix.sync.aligned.m8n8.x4.shared.b16 {%0,%1,%2,%3}, [%4];" \
        : "=r"((r)[0]), "=r"((r)[1]), "=r"((r)[2]), "=r"((r)[3]) : "r"(addr))

__device__ __forceinline__ void mma16816(float* c, const uint32_t* a,
                                         uint32_t b0, uint32_t b1) {
    asm("mma.sync.aligned.m16n8k16.row.col.f32.bf16.bf16.f32 "
        "{%0,%1,%2,%3}, {%4,%5,%6,%7}, {%8,%9}, {%0,%1,%2,%3};"
        : "+f"(c[0]), "+f"(c[1]), "+f"(c[2]), "+f"(c[3])
        : "r"(a[0]), "r"(a[1]), "r"(a[2]), "r"(a[3]), "r"(b0), "r"(b1));
}

#define CP_ASYNC16(dst, src) \
    asm volatile("cp.async.cg.shared.global [%0], [%1], 16;" \
        :: "r"(dst), "l"(src) : "memory")
#define CP_COMMIT() asm volatile("cp.async.commit_group;" ::: "memory")
#define CP_WAIT0()  asm volatile("cp.async.wait_group 0;" ::: "memory")

// ---------------------------------------------------------------------------
__global__ void __launch_bounds__(256) nb_precompute(
    const float* __restrict__ mus,
    const float* __restrict__ sigmas,
    const float* __restrict__ priors)
{
    const int r = blockIdx.x;
    const int t = threadIdx.x;
    __shared__ float red[256];

    float csum = 0.0f;
    #pragma unroll
    for (int d = t; d < TWO_D; d += 256) {
        float mu = mus[r * TWO_D + d];
        float s  = sigmas[r * TWO_D + d];
        float inv = 1.0f / (s * s);
        g_B[r * KDIM + d]         = __float2bfloat16_rn(mu * inv);
        g_B[r * KDIM + TWO_D + d] = __float2bfloat16_rn(-0.5f * inv);
        csum += -0.5f * mu * mu * inv - logf(s);
    }
    red[t] = csum;
    __syncthreads();
    #pragma unroll
    for (int s2 = 128; s2 > 0; s2 >>= 1) {
        if (t < s2) red[t] += red[t + s2];
        __syncthreads();
    }
    if (t == 0) {
        g_C[r] = red[0] - (float)TWO_D * 0.9189385332046727f
                        + priors[r] * (float)TWO_D;
    }
}

// ---------------------------------------------------------------------------
// grid = 1024: bid = ks*256 + nt*128 + mt. Each CTA: BM=32 x BN=64, K=256
// (4 chunks of 64). 4 warps, warp tile 16x32.
// ---------------------------------------------------------------------------
__global__ void __launch_bounds__(128) nb_mma_split(
    const float* __restrict__ sbjs,
    const float* __restrict__ objs)
{
    __shared__ __align__(16) char smA[2 * 2 * A_TILE];  // [stage][hi/lo]
    __shared__ __align__(16) char smB[2 * B_TILE];      // [stage]

    const int tid  = threadIdx.x;
    const int lane = tid & 31;
    const int wid  = tid >> 5;
    const int wm   = wid & 1;
    const int wn   = wid >> 1;
    const int bid  = blockIdx.x;
    const int mt   = bid & 127;
    const int nt   = (bid >> 7) & 1;
    const int ks   = bid >> 8;
    const int b0   = mt * 32;
    const int n0   = nt * 64;

    const uint32_t sA = smem_u32(smA);
    const uint32_t sB = smem_u32(smB);

    float acc[4][4];
    #pragma unroll
    for (int f = 0; f < 4; f++)
        #pragma unroll
        for (int i = 0; i < 4; i++) acc[f][i] = 0.0f;

    const int xrow  = tid >> 2;
    const int xc    = tid & 3;
    const int brow  = tid >> 1;
    const int bseg0 = (tid & 1) * 4;

    float4 xv[4];

    auto ldgX = [&](int gc) {
        const float4* src = (const float4*)(((gc >> 2) & 1) ? objs : sbjs);
        const float4* p = src + (size_t)(b0 + xrow) * (EMB / 4)
                              + (gc & 3) * 16 + xc;
        #pragma unroll
        for (int j = 0; j < 4; j++) xv[j] = p[4 * j];
    };
    auto cpB = [&](int gc, int stage) {
        const __nv_bfloat16* gp = g_B + (size_t)(n0 + brow) * KDIM
                                      + gc * 64 + bseg0 * 8;
        uint32_t dst = sB + stage * B_TILE + brow * ROWB + bseg0 * 16;
        #pragma unroll
        for (int j = 0; j < 4; j++)
            CP_ASYNC16(dst + j * 16, gp + j * 8);
        CP_COMMIT();
    };

    ldgX(ks * 4);
    cpB(ks * 4, 0);

    const uint32_t aBase = sA + (wm * 16 + (lane & 15)) * ROWB
                              + (lane >> 4) * 16;
    const uint32_t bBase = sB + (wn * 32 + (lane & 7) + ((lane >> 4) << 3)) * ROWB
                              + ((lane >> 3) & 1) * 16;

    for (int c = 0; c < 4; c++) {
        const int gc    = ks * 4 + c;
        const int stage = c & 1;
        const bool sq   = (gc >= 8);

        #pragma unroll
        for (int j = 0; j < 4; j++) {
            float4 v = xv[j];
            if (sq) { v.x *= v.x; v.y *= v.y; v.z *= v.z; v.w *= v.w; }
            __nv_bfloat16 h0 = __float2bfloat16_rn(v.x);
            __nv_bfloat16 h1 = __float2bfloat16_rn(v.y);
            __nv_bfloat16 h2 = __float2bfloat16_rn(v.z);
            __nv_bfloat16 h3 = __float2bfloat16_rn(v.w);
            __nv_bfloat16 l0 = __float2bfloat16_rn(v.x - __bfloat162float(h0));
            __nv_bfloat16 l1 = __float2bfloat16_rn(v.y - __bfloat162float(h1));
            __nv_bfloat16 l2 = __float2bfloat16_rn(v.z - __bfloat162float(h2));
            __nv_bfloat16 l3 = __float2bfloat16_rn(v.w - __bfloat162float(h3));
            uint2 hi, lo;
            hi.x = (uint32_t)__bfloat16_as_ushort(h0)
                 | ((uint32_t)__bfloat16_as_ushort(h1) << 16);
            hi.y = (uint32_t)__bfloat16_as_ushort(h2)
                 | ((uint32_t)__bfloat16_as_ushort(h3) << 16);
            lo.x = (uint32_t)__bfloat16_as_ushort(l0)
                 | ((uint32_t)__bfloat16_as_ushort(l1) << 16);
            lo.y = (uint32_t)__bfloat16_as_ushort(l2)
                 | ((uint32_t)__bfloat16_as_ushort(l3) << 16);
            int off = xrow * ROWB + (xc + 4 * j) * 8;
            *(uint2*)(smA + stage * (2 * A_TILE) + off)          = hi;
            *(uint2*)(smA + stage * (2 * A_TILE) + A_TILE + off) = lo;
        }

        CP_WAIT0();
        __syncthreads();

        if (c < 3) {
            ldgX(gc + 1);
            cpB(gc + 1, stage ^ 1);
        }

        const uint32_t aH = aBase + stage * (2 * A_TILE);
        const uint32_t aL = aH + A_TILE;
        const uint32_t bA = bBase + stage * B_TILE;

        #pragma unroll
        for (int kk = 0; kk < 4; kk++) {
            uint32_t ah[4], al[4], br0[4], br1[4];
            LDSM4(ah, aH + kk * 32);
            LDSM4(al, aL + kk * 32);
            LDSM4(br0, bA + kk * 32);
            LDSM4(br1, bA + 16 * ROWB + kk * 32);
            mma16816(acc[0], ah, br0[0], br0[1]);
            mma16816(acc[1], ah, br0[2], br0[3]);
            mma16816(acc[2], ah, br1[0], br1[1]);
            mma16816(acc[3], ah, br1[2], br1[3]);
            mma16816(acc[0], al, br0[0], br0[1]);
            mma16816(acc[1], al, br0[2], br0[3]);
            mma16816(acc[2], al, br1[0], br1[1]);
            mma16816(acc[3], al, br1[2], br1[3]);
        }
    }

    // ---- epilogue: write fp32 partials (no C here) ----
    float* pout = g_partial + (size_t)ks * (BATCH * NREL);
    const int r0 = b0 + wm * 16 + (lane >> 2);
    #pragma unroll
    for (int f = 0; f < 4; f++) {
        int col = n0 + wn * 32 + f * 8 + (lane & 3) * 2;
        *(float2*)&pout[(size_t)r0 * NREL + col] =
            make_float2(acc[f][0], acc[f][1]);
        *(float2*)&pout[(size_t)(r0 + 8) * NREL + col] =
            make_float2(acc[f][2], acc[f][3]);
    }
}

// ---------------------------------------------------------------------------
// out = sum_ks partial[ks] + C  (vectorized float4; fixed order = deterministic)
// ---------------------------------------------------------------------------
__global__ void __launch_bounds__(256) nb_reduce(float* __restrict__ out)
{
    const int idx = blockIdx.x * 256 + threadIdx.x;     // float4 index
    const int P   = BATCH * NREL / 4;                   // 131072
    const float4* p = (const float4*)g_partial;
    float4 a = p[idx];
    float4 b = p[idx + P];
    float4 c = p[idx + 2 * P];
    float4 d = p[idx + 3 * P];
    float4 C = ((const float4*)g_C)[idx & (NREL / 4 - 1)];
    float4 o;
    o.x = a.x + b.x + c.x + d.x + C.x;
    o.y = a.y + b.y + c.y + d.y + C.y;
    o.z = a.z + b.z + c.z + d.z + C.z;
    o.w = a.w + b.w + c.w + d.w + C.w;
    ((float4*)out)[idx] = o;
}

extern "C" void kernel_launch(void* const* d_in, const int* in_sizes, int n_in,
                              void* d_out, int out_size)
{
    const float* sbjs   = (const float*)d_in[0];
    const float* objs   = (const float*)d_in[1];
    const float* mus    = (const float*)d_in[2];
    const float* sigmas = (const float*)d_in[3];
    const float* priors = (const float*)d_in[4];
    float* out = (float*)d_out;

    nb_precompute<<<NREL, 256>>>(mus, sigmas, priors);
    nb_mma_split<<<KSPLIT * (BATCH / 32) * (NREL / 64), 128>>>(sbjs, objs);
    nb_reduce<<<(BATCH * NREL / 4) / 256, 256>>>(out);
}

// round 5
// speedup vs baseline: 2.9277x; 1.1807x over previous
#include <cuda_runtime.h>
#include <cuda_bf16.h>
#include <cstdint>

// out[b,r] = sum_k Xa[b,k]*G[k,r] + C[r]
//   Xa[b,k] = x[b,k] (k<512), x[b,k-512]^2 (k>=512), x = concat(sbjs, objs)
//   G[k,r]  = mu[r,k]/sig^2 (k<512), -0.5/sig^2 (k>=512)
//   C[r]    = sum_d(-0.5*mu^2/sig^2 - log sig) - 512*LOG_SQRT_2PI + 512*prior[r]
// mma.sync m16n8k16 bf16 (single bf16 A and B; measured error budget has >10x
// margin). K-split x4 across CTAs for occupancy; fp32 partials in device
// scratch; deterministic fixed-order reduce adds partials + C.

#define BATCH 4096
#define EMB   256
#define TWO_D 512
#define NREL  128
#define KDIM  1024
#define KSPLIT 4

#define ROWB   144              // smem row pitch bytes (64 data halves + 8 pad)
#define A_TILE (32 * ROWB)      // 4608 B
#define B_TILE (64 * ROWB)      // 9216 B

__device__ __nv_bfloat16 g_B[NREL * KDIM];            // 256 KB (L2-resident)
__device__ float g_C[NREL];
__device__ float g_partial[KSPLIT * BATCH * NREL];    // 8 MB scratch

__device__ __forceinline__ uint32_t smem_u32(const void* p) {
    uint32_t a;
    asm("{ .reg .u64 t; cvta.to.shared.u64 t, %1; cvt.u32.u64 %0, t; }"
        : "=r"(a) : "l"(p));
    return a;
}

#define LDSM4(r, addr) \
    asm volatile("ldmatrix.sync.aligned.m8n8.x4.shared.b16 {%0,%1,%2,%3}, [%4];" \
        : "=r"((r)[0]), "=r"((r)[1]), "=r"((r)[2]), "=r"((r)[3]) : "r"(addr))

__device__ __forceinline__ void mma16816(float* c, const uint32_t* a,
                                         uint32_t b0, uint32_t b1) {
    asm("mma.sync.aligned.m16n8k16.row.col.f32.bf16.bf16.f32 "
        "{%0,%1,%2,%3}, {%4,%5,%6,%7}, {%8,%9}, {%0,%1,%2,%3};"
        : "+f"(c[0]), "+f"(c[1]), "+f"(c[2]), "+f"(c[3])
        : "r"(a[0]), "r"(a[1]), "r"(a[2]), "r"(a[3]), "r"(b0), "r"(b1));
}

#define CP_ASYNC16(dst, src) \
    asm volatile("cp.async.cg.shared.global [%0], [%1], 16;" \
        :: "r"(dst), "l"(src) : "memory")
#define CP_COMMIT() asm volatile("cp.async.commit_group;" ::: "memory")
#define CP_WAIT0()  asm volatile("cp.async.wait_group 0;" ::: "memory")

// ---------------------------------------------------------------------------
// Precompute: one CTA per relation, one thread per dim, shuffle reduction.
// ---------------------------------------------------------------------------
__global__ void __launch_bounds__(TWO_D) nb_precompute(
    const float* __restrict__ mus,
    const float* __restrict__ sigmas,
    const float* __restrict__ priors)
{
    const int r = blockIdx.x;
    const int t = threadIdx.x;           // 0..511 == d
    __shared__ float red[16];

    float mu = mus[r * TWO_D + t];
    float s  = sigmas[r * TWO_D + t];
    float inv = 1.0f / (s * s);
    g_B[r * KDIM + t]         = __float2bfloat16_rn(mu * inv);
    g_B[r * KDIM + TWO_D + t] = __float2bfloat16_rn(-0.5f * inv);

    float c = fmaf(-0.5f * mu, mu * inv, -__logf(s));
    #pragma unroll
    for (int o = 16; o > 0; o >>= 1)
        c += __shfl_xor_sync(0xffffffffu, c, o);
    if ((t & 31) == 0) red[t >> 5] = c;
    __syncthreads();
    if (t < 32) {
        float v = (t < 16) ? red[t] : 0.0f;
        #pragma unroll
        for (int o = 8; o > 0; o >>= 1)
            v += __shfl_xor_sync(0xffffffffu, v, o);
        if (t == 0)
            g_C[r] = v - (float)TWO_D * 0.9189385332046727f
                       + priors[r] * (float)TWO_D;
    }
}

// ---------------------------------------------------------------------------
// grid = 1024: bid = ks*256 + nt*128 + mt. Each CTA: BM=32 x BN=64, K=256
// (4 chunks of 64). 4 warps, warp tile 16x32.
// ---------------------------------------------------------------------------
__global__ void __launch_bounds__(128) nb_mma_split(
    const float* __restrict__ sbjs,
    const float* __restrict__ objs)
{
    __shared__ __align__(16) char smA[2 * A_TILE];      // [stage]
    __shared__ __align__(16) char smB[2 * B_TILE];      // [stage]

    const int tid  = threadIdx.x;
    const int lane = tid & 31;
    const int wid  = tid >> 5;
    const int wm   = wid & 1;
    const int wn   = wid >> 1;
    const int bid  = blockIdx.x;
    const int mt   = bid & 127;
    const int nt   = (bid >> 7) & 1;
    const int ks   = bid >> 8;
    const int b0   = mt * 32;
    const int n0   = nt * 64;

    const uint32_t sA = smem_u32(smA);
    const uint32_t sB = smem_u32(smB);

    float acc[4][4];
    #pragma unroll
    for (int f = 0; f < 4; f++)
        #pragma unroll
        for (int i = 0; i < 4; i++) acc[f][i] = 0.0f;

    const int xrow  = tid >> 2;
    const int xc    = tid & 3;
    const int brow  = tid >> 1;
    const int bseg0 = (tid & 1) * 4;

    float4 xv[4];

    auto ldgX = [&](int gc) {
        const float4* src = (const float4*)(((gc >> 2) & 1) ? objs : sbjs);
        const float4* p = src + (size_t)(b0 + xrow) * (EMB / 4)
                              + (gc & 3) * 16 + xc;
        #pragma unroll
        for (int j = 0; j < 4; j++) xv[j] = p[4 * j];
    };
    auto cpB = [&](int gc, int stage) {
        const __nv_bfloat16* gp = g_B + (size_t)(n0 + brow) * KDIM
                                      + gc * 64 + bseg0 * 8;
        uint32_t dst = sB + stage * B_TILE + brow * ROWB + bseg0 * 16;
        #pragma unroll
        for (int j = 0; j < 4; j++)
            CP_ASYNC16(dst + j * 16, gp + j * 8);
        CP_COMMIT();
    };

    ldgX(ks * 4);
    cpB(ks * 4, 0);

    const uint32_t aBase = sA + (wm * 16 + (lane & 15)) * ROWB
                              + (lane >> 4) * 16;
    const uint32_t bBase = sB + (wn * 32 + (lane & 7) + ((lane >> 4) << 3)) * ROWB
                              + ((lane >> 3) & 1) * 16;

    for (int c = 0; c < 4; c++) {
        const int gc    = ks * 4 + c;
        const int stage = c & 1;
        const bool sq   = (gc >= 8);

        #pragma unroll
        for (int j = 0; j < 4; j++) {
            float4 v = xv[j];
            if (sq) { v.x *= v.x; v.y *= v.y; v.z *= v.z; v.w *= v.w; }
            __nv_bfloat16 h0 = __float2bfloat16_rn(v.x);
            __nv_bfloat16 h1 = __float2bfloat16_rn(v.y);
            __nv_bfloat16 h2 = __float2bfloat16_rn(v.z);
            __nv_bfloat16 h3 = __float2bfloat16_rn(v.w);
            uint2 hi;
            hi.x = (uint32_t)__bfloat16_as_ushort(h0)
                 | ((uint32_t)__bfloat16_as_ushort(h1) << 16);
            hi.y = (uint32_t)__bfloat16_as_ushort(h2)
                 | ((uint32_t)__bfloat16_as_ushort(h3) << 16);
            int off = xrow * ROWB + (xc + 4 * j) * 8;
            *(uint2*)(smA + stage * A_TILE + off) = hi;
        }

        CP_WAIT0();
        __syncthreads();

        if (c < 3) {
            ldgX(gc + 1);
            cpB(gc + 1, stage ^ 1);
        }

        const uint32_t aH = aBase + stage * A_TILE;
        const uint32_t bA = bBase + stage * B_TILE;

        #pragma unroll
        for (int kk = 0; kk < 4; kk++) {
            uint32_t ah[4], br0[4], br1[4];
            LDSM4(ah, aH + kk * 32);
            LDSM4(br0, bA + kk * 32);
            LDSM4(br1, bA + 16 * ROWB + kk * 32);
            mma16816(acc[0], ah, br0[0], br0[1]);
            mma16816(acc[1], ah, br0[2], br0[3]);
            mma16816(acc[2], ah, br1[0], br1[1]);
            mma16816(acc[3], ah, br1[2], br1[3]);
        }
    }

    // ---- epilogue: write fp32 partials (no C here) ----
    float* pout = g_partial + (size_t)ks * (BATCH * NREL);
    const int r0 = b0 + wm * 16 + (lane >> 2);
    #pragma unroll
    for (int f = 0; f < 4; f++) {
        int col = n0 + wn * 32 + f * 8 + (lane & 3) * 2;
        *(float2*)&pout[(size_t)r0 * NREL + col] =
            make_float2(acc[f][0], acc[f][1]);
        *(float2*)&pout[(size_t)(r0 + 8) * NREL + col] =
            make_float2(acc[f][2], acc[f][3]);
    }
}

// ---------------------------------------------------------------------------
// out = sum_ks partial[ks] + C  (float4; fixed order = deterministic)
// ---------------------------------------------------------------------------
__global__ void __launch_bounds__(256) nb_reduce(float* __restrict__ out)
{
    const int idx = blockIdx.x * 256 + threadIdx.x;     // float4 index
    const int P   = BATCH * NREL / 4;                   // 131072
    const float4* p = (const float4*)g_partial;
    float4 a = p[idx];
    float4 b = p[idx + P];
    float4 c = p[idx + 2 * P];
    float4 d = p[idx + 3 * P];
    float4 C = ((const float4*)g_C)[idx & (NREL / 4 - 1)];
    float4 o;
    o.x = a.x + b.x + c.x + d.x + C.x;
    o.y = a.y + b.y + c.y + d.y + C.y;
    o.z = a.z + b.z + c.z + d.z + C.z;
    o.w = a.w + b.w + c.w + d.w + C.w;
    ((float4*)out)[idx] = o;
}

extern "C" void kernel_launch(void* const* d_in, const int* in_sizes, int n_in,
                              void* d_out, int out_size)
{
    const float* sbjs   = (const float*)d_in[0];
    const float* objs   = (const float*)d_in[1];
    const float* mus    = (const float*)d_in[2];
    const float* sigmas = (const float*)d_in[3];
    const float* priors = (const float*)d_in[4];
    float* out = (float*)d_out;

    nb_precompute<<<NREL, TWO_D>>>(mus, sigmas, priors);
    nb_mma_split<<<KSPLIT * (BATCH / 32) * (NREL / 64), 128>>>(sbjs, objs);
    nb_reduce<<<(BATCH * NREL / 4) / 256, 256>>>(out);
}